// round 5
// baseline (speedup 1.0000x reference)
#include <cuda_runtime.h>
#include <cuda_fp16.h>
#include <math.h>
#include <stdint.h>

#define DIMM   2048
#define NHEADS 16
#define HDIM   128
#define SEQL   1024
#define BS     2
#define ALEN   10
#define MAXF   10
#define KCAT   1152   /* 10 adapter + 1024 keys + 118 zero pad = 9*128 */

// ---------------- scratch (device globals; no allocation allowed) ----------
__device__ float  g_QKV[3*BS*SEQL*DIMM];     // fp32 Q|K|V slices
__device__ float  g_S [BS*NHEADS*SEQL*KCAT];
__device__ float  g_ak[ALEN*DIMM];
__device__ float  g_av[ALEN*DIMM];
__device__ __half g_xh [BS*SEQL*DIMM];
__device__ __half g_wh [3*DIMM*DIMM];        // wq|wk|wv fp16
__device__ __half g_woh[DIMM*DIMM];
__device__ __half g_Qh [BS*SEQL*DIMM];
__device__ __half g_Kch[BS*NHEADS*KCAT*HDIM];
__device__ __half g_Vth[BS*NHEADS*HDIM*KCAT];   // V transposed: [z][d][k]
__device__ __half g_Ph [BS*NHEADS*SEQL*KCAT];
__device__ __half g_Oh [BS*SEQL*DIMM];

// ---------------- PTX helpers ----------------------------------------------
__device__ __forceinline__ uint32_t smem_to_u32(const void* p) {
    uint32_t a;
    asm("{ .reg .u64 t; cvta.to.shared.u64 t, %1; cvt.u32.u64 %0, t; }" : "=r"(a) : "l"(p));
    return a;
}
#define CP16(dst, src) \
    asm volatile("cp.async.cg.shared.global [%0], [%1], 16;" :: "r"(dst), "l"(src))
#define CP_COMMIT() asm volatile("cp.async.commit_group;" ::: "memory")
#define CP_WAIT2()  asm volatile("cp.async.wait_group 2;" ::: "memory")

#define LDSM4(r, a) \
    asm volatile("ldmatrix.sync.aligned.m8n8.x4.shared.b16 {%0,%1,%2,%3},[%4];" \
        : "=r"((r)[0]), "=r"((r)[1]), "=r"((r)[2]), "=r"((r)[3]) : "r"(a))

__device__ __forceinline__ void mma16(float* c, const uint32_t* a, uint32_t b0, uint32_t b1) {
    asm volatile(
        "mma.sync.aligned.m16n8k16.row.col.f32.f16.f16.f32 "
        "{%0,%1,%2,%3},{%4,%5,%6,%7},{%8,%9},{%0,%1,%2,%3};"
        : "+f"(c[0]), "+f"(c[1]), "+f"(c[2]), "+f"(c[3])
        : "r"(a[0]), "r"(a[1]), "r"(a[2]), "r"(a[3]), "r"(b0), "r"(b1));
}

// ---------------- fp16 tensor-core batched GEMM: C = A @ B^T ----------------
// CTA tile 256(M) x 128(N), 8 warps (4m x 2n), warp tile 64x64, BK=32, 4-stage.
// A: (M,K) half row-major, B: (N,K) half row-major. M%256==0, N%128==0, K%32==0.
// smem rows have 80B pitch (64B data + 16B pad) -> conflict-free ldmatrix.
#define HG_ABYTES 20480          /* 256 rows x 80B */
#define HG_STAGE  30720          /* A 20480 + B 10240 */
#define HG_SMEM   122880         /* 4 stages */

template <typename OutT, bool CAUSAL, bool TRUNC>
__global__ __launch_bounds__(256) void hgemm(
    const __half* __restrict__ A, const __half* __restrict__ B, OutT* __restrict__ C,
    int K, int lda, int ldb, int ldc,
    long long aSb, long long aSh, long long bSb, long long bSh,
    long long cSb, long long cSh, int nh)
{
    const int m0 = blockIdx.y * 256, n0 = blockIdx.x * 128;
    if (CAUSAL && n0 > m0 + 255 + ALEN) return;   // fully-masked score tile

    extern __shared__ char smem[];
    const uint32_t sb = smem_to_u32(smem);
    int zb = blockIdx.z / nh, zh = blockIdx.z % nh;
    A += zb*aSb + zh*aSh;
    B += zb*bSb + zh*bSh;
    C += zb*cSb + zh*cSh;

    const int tid = threadIdx.x, lane = tid & 31, warp = tid >> 5;
    const int wm = warp & 3, wn = warp >> 2;       // warp tile 64(m) x 64(n)

    int Keff = TRUNC ? min(K, (m0 + 256 + ALEN + 31) & ~31) : K;
    const int nch = Keff >> 5;                     // >= 4 for all our shapes

    // copy mapping: A row=tid (4x16B), B row=tid&127, 2x16B at (tid>>7)*32B
    const __half* ag = A + (long long)(m0 + tid) * lda;
    const __half* bg = B + (long long)(n0 + (tid & 127)) * ldb + (tid >> 7) * 16;
    const uint32_t sa  = sb + tid * 80;
    const uint32_t sbb = sb + HG_ABYTES + (tid & 127) * 80 + (tid >> 7) * 32;

    float acc[4][8][4];
    #pragma unroll
    for (int mi = 0; mi < 4; mi++)
        #pragma unroll
        for (int ni = 0; ni < 8; ni++)
            #pragma unroll
            for (int j = 0; j < 4; j++) acc[mi][ni][j] = 0.f;

    // prologue: stages 0..2
    #pragma unroll
    for (int s = 0; s < 3; s++) {
        #pragma unroll
        for (int i = 0; i < 4; i++) CP16(sa + s*HG_STAGE + i*16, ag + s*32 + i*8);
        #pragma unroll
        for (int i = 0; i < 2; i++) CP16(sbb + s*HG_STAGE + i*16, bg + s*32 + i*8);
        CP_COMMIT();
    }

    const int rsel = lane & 15, csel = lane >> 4;

    for (int c = 0; c < nch; c++) {
        CP_WAIT2();
        __syncthreads();
        int nxt = c + 3;
        if (nxt < nch) {
            int s = nxt & 3;
            #pragma unroll
            for (int i = 0; i < 4; i++) CP16(sa + s*HG_STAGE + i*16, ag + nxt*32 + i*8);
            #pragma unroll
            for (int i = 0; i < 2; i++) CP16(sbb + s*HG_STAGE + i*16, bg + nxt*32 + i*8);
        }
        CP_COMMIT();

        const uint32_t abase = sb + (c & 3)*HG_STAGE + (wm*64)*80;
        const uint32_t bbase = sb + (c & 3)*HG_STAGE + HG_ABYTES + (wn*64)*80;
        #pragma unroll
        for (int ks = 0; ks < 2; ks++) {
            uint32_t a[4][4], b[4][4];
            #pragma unroll
            for (int mi = 0; mi < 4; mi++)
                LDSM4(a[mi], abase + (mi*16 + rsel)*80 + ks*32 + csel*16);
            #pragma unroll
            for (int nj = 0; nj < 4; nj++)
                LDSM4(b[nj], bbase + (nj*16 + rsel)*80 + ks*32 + csel*16);
            #pragma unroll
            for (int mi = 0; mi < 4; mi++)
                #pragma unroll
                for (int ni = 0; ni < 8; ni++)
                    mma16(acc[mi][ni], a[mi], b[ni>>1][ni&1], b[ni>>1][(ni&1)+2]);
        }
    }

    const int er = lane >> 2, ec = (lane & 3) * 2;
    #pragma unroll
    for (int mi = 0; mi < 4; mi++) {
        #pragma unroll
        for (int ni = 0; ni < 8; ni++) {
            int row = m0 + wm*64 + mi*16 + er;
            int col = n0 + wn*64 + ni*8 + ec;
            float* cc = acc[mi][ni];
            if (sizeof(OutT) == 4) {
                *(float2*)((float*)C + (long long)row * ldc + col) = make_float2(cc[0], cc[1]);
                *(float2*)((float*)C + (long long)(row+8) * ldc + col) = make_float2(cc[2], cc[3]);
            } else {
                *(__half2*)((__half*)C + (long long)row * ldc + col) = __floats2half2_rn(cc[0], cc[1]);
                *(__half2*)((__half*)C + (long long)(row+8) * ldc + col) = __floats2half2_rn(cc[2], cc[3]);
            }
        }
    }
}

// ---------------- fp32 -> fp16 conversion -----------------------------------
__global__ void f2h_kernel(const float* __restrict__ in, __half* __restrict__ out) {
    int i = blockIdx.x * 256 + threadIdx.x;
    float4 v = ((const float4*)in)[i];
    ((__half2*)out)[2*i]   = __floats2half2_rn(v.x, v.y);
    ((__half2*)out)[2*i+1] = __floats2half2_rn(v.z, v.w);
}

// ---------------- adapter projections (wk & wv in one launch, fp32) ---------
__global__ __launch_bounds__(256) void adapter_proj2(const float* __restrict__ adp,
                                                     const float* __restrict__ wk,
                                                     const float* __restrict__ wv)
{
    const int lane = threadIdx.x & 31;
    const int n = blockIdx.x * 8 + (threadIdx.x >> 5);
    const float* w = blockIdx.y ? wv : wk;
    float* out = blockIdx.y ? g_av : g_ak;

    float acc[ALEN];
    #pragma unroll
    for (int j = 0; j < ALEN; j++) acc[j] = 0.f;

    const float4* wr = (const float4*)(w + (long long)n * DIMM);
    for (int k4 = lane; k4 < DIMM/4; k4 += 32) {
        float4 wv4 = wr[k4];
        #pragma unroll
        for (int j = 0; j < ALEN; j++) {
            float4 a4 = ((const float4*)(adp + j * DIMM))[k4];
            acc[j] += a4.x*wv4.x + a4.y*wv4.y + a4.z*wv4.z + a4.w*wv4.w;
        }
    }
    #pragma unroll
    for (int j = 0; j < ALEN; j++) {
        float v = acc[j];
        #pragma unroll
        for (int o = 16; o > 0; o >>= 1) v += __shfl_xor_sync(0xffffffffu, v, o);
        if (lane == 0) out[j * DIMM + n] = v;
    }
}

// ---------------- RoPE on Q: fp32 in -> fp16 out ----------------------------
__global__ void rope_q_kernel(const float* __restrict__ Q, __half* __restrict__ Qh,
                              const float* __restrict__ cs, const float* __restrict__ sn)
{
    int idx = blockIdx.x * blockDim.x + threadIdx.x;   // BS*SEQL*NHEADS*64
    int p = idx & 63;
    int h = (idx >> 6) & 15;
    int r = idx >> 10;
    int q = r & 1023;
    float c = cs[q*64 + p], s = sn[q*64 + p];
    long long base = (long long)r * DIMM + h * HDIM + 2*p;
    float xr = Q[base], xi = Q[base + 1];
    *(__half2*)(Qh + base) = __floats2half2_rn(xr*c - xi*s, xr*s + xi*c);
}

// ---------------- build Kc (rope fused, adapter rows un-roped) -> fp16 ------
__global__ void build_kc_kernel(const float* __restrict__ K,
                                const float* __restrict__ cs, const float* __restrict__ sn)
{
    int idx = blockIdx.x * blockDim.x + threadIdx.x;   // BS*NHEADS*KCAT*64
    int p = idx & 63;
    int rz = idx >> 6;
    int r = rz % KCAT;
    int z = rz / KCAT;
    int b = z >> 4, h = z & 15;
    __half2 out = __floats2half2_rn(0.f, 0.f);
    if (r < ALEN) {
        out = __floats2half2_rn(g_ak[r*DIMM + h*HDIM + 2*p], g_ak[r*DIMM + h*HDIM + 2*p + 1]);
    } else if (r < ALEN + SEQL) {
        int q = r - ALEN;
        float c = cs[q*64 + p], s = sn[q*64 + p];
        long long base = (long long)(b*SEQL + q) * DIMM + h*HDIM + 2*p;
        float xr = K[base], xi = K[base + 1];
        out = __floats2half2_rn(xr*c - xi*s, xr*s + xi*c);
    }
    *(__half2*)(g_Kch + (long long)z*KCAT*HDIM + r*HDIM + 2*p) = out;
}

// ---------------- transposed [adapter|values|pad] V -> fp16 g_Vth[z][d][k] --
__global__ void transpose_v_kernel(const float* __restrict__ V)
{
    __shared__ float tile[32][33];
    int z = blockIdx.z;
    int b = z >> 4, h = z & 15;
    int kt = blockIdx.x * 32, dt = blockIdx.y * 32;
    int tx = threadIdx.x, ty = threadIdx.y;   // 32 x 8
    #pragma unroll
    for (int j = 0; j < 4; j++) {
        int k = kt + ty + 8*j;
        int d = dt + tx;
        float v = 0.f;
        if (k < ALEN) v = g_av[k * DIMM + h * HDIM + d];
        else if (k < ALEN + SEQL)
            v = V[((long long)(b * SEQL + k - ALEN)) * DIMM + h * HDIM + d];
        tile[ty + 8*j][tx] = v;
    }
    __syncthreads();
    #pragma unroll
    for (int j = 0; j < 4; j++) {
        int d = dt + ty + 8*j;
        g_Vth[((long long)z * HDIM + d) * KCAT + kt + tx] = __float2half(tile[tx][ty + 8*j]);
    }
}

// ---------------- softmax: fp32 scores in, fp16 probs out -------------------
__global__ void softmax_kernel(const float* __restrict__ S,
                               const float* __restrict__ gate1,
                               const float* __restrict__ gate2,
                               const int*   __restrict__ vsp)
{
    int z = blockIdx.x >> 10;
    int q = blockIdx.x & 1023;
    int h = z & 15;
    const float* row = S + (long long)blockIdx.x * KCAT;
    __half* hrow = g_Ph + (long long)blockIdx.x * KCAT;
    int tid = threadIdx.x;
    int vs = *vsp;
    const float scale = 0.08838834764831843f;   // 1/sqrt(128)
    float g2 = gate2[h];
    bool grow = (q >= vs + MAXF);

    float vals[4];
    float lmax = -1e30f;
    #pragma unroll
    for (int i = 0; i < 4; i++) {
        int k = tid + i * 256;
        float v = -1e30f;
        if (k <= q) {
            v = row[ALEN + k] * scale;
            if (grow && k >= vs && k < vs + MAXF) v += g2;
        }
        vals[i] = v;  lmax = fmaxf(lmax, v);
    }
    __shared__ float red[256];
    red[tid] = lmax; __syncthreads();
    for (int s = 128; s > 0; s >>= 1) {
        if (tid < s) red[tid] = fmaxf(red[tid], red[tid + s]);
        __syncthreads();
    }
    float rmax = red[0]; __syncthreads();

    float lsum = 0.f;
    #pragma unroll
    for (int i = 0; i < 4; i++) {
        int k = tid + i * 256;
        float e = (k <= q) ? expf(vals[i] - rmax) : 0.f;
        vals[i] = e;  lsum += e;
    }
    red[tid] = lsum; __syncthreads();
    for (int s = 128; s > 0; s >>= 1) {
        if (tid < s) red[tid] += red[tid + s];
        __syncthreads();
    }
    float inv = 1.0f / red[0];

    #pragma unroll
    for (int i = 0; i < 4; i++) {
        int k = tid + i * 256;
        hrow[ALEN + k] = __float2half(vals[i] * inv);
    }
    if (tid < KCAT - ALEN - SEQL) hrow[ALEN + SEQL + tid] = __float2half(0.f);

    if (tid == 0) {
        float g1 = tanhf(gate1[h]);
        float a[ALEN]; float am = -1e30f;
        #pragma unroll
        for (int j = 0; j < ALEN; j++) { a[j] = row[j] * scale; am = fmaxf(am, a[j]); }
        float s = 0.f;
        #pragma unroll
        for (int j = 0; j < ALEN; j++) { a[j] = expf(a[j] - am); s += a[j]; }
        float sc = g1 / s;
        #pragma unroll
        for (int j = 0; j < ALEN; j++) hrow[j] = __float2half(a[j] * sc);
    }
}

// ---------------- launch -----------------------------------------------------
extern "C" void kernel_launch(void* const* d_in, const int* in_sizes, int n_in,
                              void* d_out, int out_size)
{
    const float* x   = (const float*)d_in[0];
    const float* adp = (const float*)d_in[1];
    /* d_in[2] = mask: equivalent to hard causal mask, recomputed on device */
    const float* fc  = (const float*)d_in[3];
    const float* fs  = (const float*)d_in[4];
    const float* wq  = (const float*)d_in[5];
    const float* wk  = (const float*)d_in[6];
    const float* wv  = (const float*)d_in[7];
    const float* wo  = (const float*)d_in[8];
    const float* g1  = (const float*)d_in[9];
    const float* g2  = (const float*)d_in[10];
    const int*   vsp = (const int*)d_in[11];
    float* out = (float*)d_out;

    float *QKVp, *Sp;
    __half *xh, *wh, *woh, *Qhp, *Kchp, *Vthp, *Php, *Ohp;
    cudaGetSymbolAddress((void**)&QKVp, g_QKV);
    cudaGetSymbolAddress((void**)&Sp,  g_S);
    cudaGetSymbolAddress((void**)&xh,  g_xh);
    cudaGetSymbolAddress((void**)&wh,  g_wh);
    cudaGetSymbolAddress((void**)&woh, g_woh);
    cudaGetSymbolAddress((void**)&Qhp, g_Qh);
    cudaGetSymbolAddress((void**)&Kchp, g_Kch);
    cudaGetSymbolAddress((void**)&Vthp, g_Vth);
    cudaGetSymbolAddress((void**)&Php, g_Ph);
    cudaGetSymbolAddress((void**)&Ohp, g_Oh);

    float* Qp = QKVp;
    float* Kp = QKVp + (long long)BS*SEQL*DIMM;
    float* Vp = QKVp + 2LL*BS*SEQL*DIMM;

    cudaFuncSetAttribute(hgemm<float,false,false>, cudaFuncAttributeMaxDynamicSharedMemorySize, HG_SMEM);
    cudaFuncSetAttribute(hgemm<float,true,false>,  cudaFuncAttributeMaxDynamicSharedMemorySize, HG_SMEM);
    cudaFuncSetAttribute(hgemm<__half,false,true>, cudaFuncAttributeMaxDynamicSharedMemorySize, HG_SMEM);

    // fp32 -> fp16 conversions (weights into one contiguous buffer)
    f2h_kernel<<<BS*SEQL*DIMM/1024, 256>>>(x, xh);
    f2h_kernel<<<DIMM*DIMM/1024, 256>>>(wq, wh);
    f2h_kernel<<<DIMM*DIMM/1024, 256>>>(wk, wh + (long long)DIMM*DIMM);
    f2h_kernel<<<DIMM*DIMM/1024, 256>>>(wv, wh + 2LL*DIMM*DIMM);
    f2h_kernel<<<DIMM*DIMM/1024, 256>>>(wo, woh);

    // QKV projections fused: z in {0,1,2} selects weight slice & output slice
    hgemm<float,false,false><<<dim3(DIMM/128, (BS*SEQL)/256, 3), 256, HG_SMEM>>>(
        xh, wh, QKVp, DIMM, DIMM, DIMM, DIMM,
        0, 0, 0, (long long)DIMM*DIMM,
        0, (long long)BS*SEQL*DIMM, 3);

    adapter_proj2<<<dim3(DIMM/8, 2), 256>>>(adp, wk, wv);

    rope_q_kernel<<<BS*SEQL*NHEADS*64/256, 256>>>(Qp, Qhp, fc, fs);
    build_kc_kernel<<<(BS*NHEADS*KCAT*64)/256, 256>>>(Kp, fc, fs);
    transpose_v_kernel<<<dim3(KCAT/32, HDIM/32, BS*NHEADS), dim3(32, 8)>>>(Vp);

    // scores: per z: S(1024x1152) = Qh(1024x128) @ Kch^T  (causal tile skip)
    hgemm<float,true,false><<<dim3(KCAT/128, SEQL/256, BS*NHEADS), 256, HG_SMEM>>>(
        Qhp, Kchp, Sp, HDIM,
        DIMM, HDIM, KCAT,
        (long long)SEQL*DIMM, (long long)HDIM,
        (long long)NHEADS*KCAT*HDIM, (long long)KCAT*HDIM,
        (long long)NHEADS*SEQL*KCAT, (long long)SEQL*KCAT, NHEADS);

    softmax_kernel<<<BS*NHEADS*SEQL, 256>>>(Sp, g1, g2, vsp);

    // attn: per z: Oh(1024x128) = Ph(1024x1152) @ Vth(128x1152)^T  (K-truncated)
    hgemm<__half,false,true><<<dim3(1, SEQL/256, BS*NHEADS), 256, HG_SMEM>>>(
        Php, Vthp, Ohp, KCAT,
        KCAT, KCAT, DIMM,
        (long long)NHEADS*SEQL*KCAT, (long long)SEQL*KCAT,
        (long long)NHEADS*HDIM*KCAT, (long long)HDIM*KCAT,
        (long long)SEQL*DIMM, (long long)HDIM, NHEADS);

    // output projection: fp32 out to d_out
    hgemm<float,false,false><<<dim3(DIMM/128, (BS*SEQL)/256, 1), 256, HG_SMEM>>>(
        Ohp, woh, out, DIMM, DIMM, DIMM, DIMM, 0,0,0,0,0,0, 1);
}

// round 6
// speedup vs baseline: 1.1749x; 1.1749x over previous
#include <cuda_runtime.h>
#include <cuda_fp16.h>
#include <math.h>
#include <stdint.h>

#define DIMM   2048
#define NHEADS 16
#define HDIM   128
#define SEQL   1024
#define BS     2
#define ALEN   10
#define MAXF   10
#define KCAT   1152   /* 10 adapter + 1024 keys + 118 zero pad = 9*128 */

// ---------------- scratch (device globals; no allocation allowed) ----------
__device__ float  g_Q [BS*SEQL*DIMM];
__device__ float  g_K [BS*SEQL*DIMM];
__device__ float  g_V [BS*SEQL*DIMM];
__device__ float  g_S [BS*NHEADS*SEQL*KCAT];
__device__ float  g_ak[ALEN*DIMM];
__device__ float  g_av[ALEN*DIMM];
__device__ __half g_xh [BS*SEQL*DIMM];
__device__ __half g_wqh[DIMM*DIMM];
__device__ __half g_wkh[DIMM*DIMM];
__device__ __half g_wvh[DIMM*DIMM];
__device__ __half g_woh[DIMM*DIMM];
__device__ __half g_Qh [BS*SEQL*DIMM];
__device__ __half g_Kch[BS*NHEADS*KCAT*HDIM];
__device__ __half g_Vth[BS*NHEADS*HDIM*KCAT];   // V transposed: [z][d][k]
__device__ __half g_Ph [BS*NHEADS*SEQL*KCAT];
__device__ __half g_Oh [BS*SEQL*DIMM];

// ---------------- PTX helpers ----------------------------------------------
__device__ __forceinline__ uint32_t smem_to_u32(const void* p) {
    uint32_t a;
    asm("{ .reg .u64 t; cvta.to.shared.u64 t, %1; cvt.u32.u64 %0, t; }" : "=r"(a) : "l"(p));
    return a;
}
#define CP16(dst, src) \
    asm volatile("cp.async.cg.shared.global [%0], [%1], 16;" :: "r"(dst), "l"(src))
#define CP_COMMIT() asm volatile("cp.async.commit_group;" ::: "memory")
#define CP_WAIT2()  asm volatile("cp.async.wait_group 2;" ::: "memory")

#define LDSM4(r, a) \
    asm volatile("ldmatrix.sync.aligned.m8n8.x4.shared.b16 {%0,%1,%2,%3},[%4];" \
        : "=r"((r)[0]), "=r"((r)[1]), "=r"((r)[2]), "=r"((r)[3]) : "r"(a))

__device__ __forceinline__ void mma16(float* c, const uint32_t* a, uint32_t b0, uint32_t b1) {
    asm volatile(
        "mma.sync.aligned.m16n8k16.row.col.f32.f16.f16.f32 "
        "{%0,%1,%2,%3},{%4,%5,%6,%7},{%8,%9},{%0,%1,%2,%3};"
        : "+f"(c[0]), "+f"(c[1]), "+f"(c[2]), "+f"(c[3])
        : "r"(a[0]), "r"(a[1]), "r"(a[2]), "r"(a[3]), "r"(b0), "r"(b1));
}

// ---------------- fp16 tensor-core batched GEMM: C = A @ B^T ----------------
// CTA tile 128x128, 8 warps (2m x 4n), warp tile 64x32, BK=32, 4-stage cp.async.
// A: (M,K) half row-major, B: (N,K) half row-major. M,N %128==0, K %32==0.
// smem rows 80B pitch (64B data + 16B pad) -> conflict-free ldmatrix.
#define HG_STAGE 20480
#define HG_SMEM  81920

template <typename OutT, bool CAUSAL, bool TRUNC>
__global__ __launch_bounds__(256) void hgemm(
    const __half* __restrict__ A, const __half* __restrict__ B, OutT* __restrict__ C,
    int K, int lda, int ldb, int ldc,
    long long aSb, long long aSh, long long bSb, long long bSh,
    long long cSb, long long cSh, int nh)
{
    const int m0 = blockIdx.y * 128, n0 = blockIdx.x * 128;
    if (CAUSAL && n0 > m0 + 127 + ALEN) return;   // fully-masked score tile

    extern __shared__ char smem[];
    const uint32_t sb = smem_to_u32(smem);
    int zb = blockIdx.z / nh, zh = blockIdx.z % nh;
    A += zb*aSb + zh*aSh;
    B += zb*bSb + zh*bSh;
    C += zb*cSb + zh*cSh;

    const int tid = threadIdx.x, lane = tid & 31, warp = tid >> 5;
    const int wm = warp & 1, wn = warp >> 1;       // warp tile 64(m) x 32(n)

    const int Keff = TRUNC ? min(K, (m0 + 128 + ALEN + 31) & ~31) : K;
    const int nch = Keff >> 5;                     // >= 4 for all our shapes

    // copy mapping: thread -> row tid>>1, two 16B segs at (tid&1)*32 bytes
    const int crow = tid >> 1;
    const int cseg = (tid & 1) * 2;
    const __half* ag = A + (long long)(m0 + crow) * lda + cseg * 8;
    const __half* bg = B + (long long)(n0 + crow) * ldb + cseg * 8;
    const uint32_t sa = sb + crow*80 + cseg*16;
    const uint32_t sbb = sb + 10240 + crow*80 + cseg*16;

    float acc[4][4][4];
    #pragma unroll
    for (int mi = 0; mi < 4; mi++)
        #pragma unroll
        for (int ni = 0; ni < 4; ni++)
            #pragma unroll
            for (int j = 0; j < 4; j++) acc[mi][ni][j] = 0.f;

    // prologue: stages 0..2
    #pragma unroll
    for (int s = 0; s < 3; s++) {
        CP16(sa  + s*HG_STAGE,      ag + s*32);
        CP16(sa  + s*HG_STAGE + 16, ag + s*32 + 8);
        CP16(sbb + s*HG_STAGE,      bg + s*32);
        CP16(sbb + s*HG_STAGE + 16, bg + s*32 + 8);
        CP_COMMIT();
    }

    const int rsel = lane & 15, csel = lane >> 4;

    for (int c = 0; c < nch; c++) {
        CP_WAIT2();
        __syncthreads();
        int nxt = c + 3;
        if (nxt < nch) {
            int s = nxt & 3;
            CP16(sa  + s*HG_STAGE,      ag + nxt*32);
            CP16(sa  + s*HG_STAGE + 16, ag + nxt*32 + 8);
            CP16(sbb + s*HG_STAGE,      bg + nxt*32);
            CP16(sbb + s*HG_STAGE + 16, bg + nxt*32 + 8);
        }
        CP_COMMIT();

        const uint32_t abase = sb + (c & 3)*HG_STAGE + (wm*64)*80;
        const uint32_t bbase = sb + (c & 3)*HG_STAGE + 10240 + (wn*32)*80;
        #pragma unroll
        for (int ks = 0; ks < 2; ks++) {
            uint32_t a[4][4], b[2][4];
            #pragma unroll
            for (int mi = 0; mi < 4; mi++)
                LDSM4(a[mi], abase + (mi*16 + rsel)*80 + ks*32 + csel*16);
            #pragma unroll
            for (int nj = 0; nj < 2; nj++)
                LDSM4(b[nj], bbase + (nj*16 + rsel)*80 + ks*32 + csel*16);
            #pragma unroll
            for (int mi = 0; mi < 4; mi++)
                #pragma unroll
                for (int ni = 0; ni < 4; ni++)
                    mma16(acc[mi][ni], a[mi], b[ni>>1][ni&1], b[ni>>1][(ni&1)+2]);
        }
    }

    const int er = lane >> 2, ec = (lane & 3) * 2;
    #pragma unroll
    for (int mi = 0; mi < 4; mi++) {
        #pragma unroll
        for (int ni = 0; ni < 4; ni++) {
            int row = m0 + wm*64 + mi*16 + er;
            int col = n0 + wn*32 + ni*8 + ec;
            float* cc = acc[mi][ni];
            if (sizeof(OutT) == 4) {
                *(float2*)((float*)C + (long long)row * ldc + col) = make_float2(cc[0], cc[1]);
                *(float2*)((float*)C + (long long)(row+8) * ldc + col) = make_float2(cc[2], cc[3]);
            } else {
                *(__half2*)((__half*)C + (long long)row * ldc + col) = __floats2half2_rn(cc[0], cc[1]);
                *(__half2*)((__half*)C + (long long)(row+8) * ldc + col) = __floats2half2_rn(cc[2], cc[3]);
            }
        }
    }
}

// ---------------- fp32 -> fp16 conversion -----------------------------------
__global__ void f2h_kernel(const float* __restrict__ in, __half* __restrict__ out) {
    int i = blockIdx.x * 256 + threadIdx.x;
    float4 v = ((const float4*)in)[i];
    ((__half2*)out)[2*i]   = __floats2half2_rn(v.x, v.y);
    ((__half2*)out)[2*i+1] = __floats2half2_rn(v.z, v.w);
}

// all 4 weight matrices in one launch; grid.y selects matrix
__global__ void f2h4_kernel(const float* __restrict__ w0, const float* __restrict__ w1,
                            const float* __restrict__ w2, const float* __restrict__ w3,
                            __half* __restrict__ o0, __half* __restrict__ o1,
                            __half* __restrict__ o2, __half* __restrict__ o3) {
    const float* in;  __half* out;
    switch (blockIdx.y) {
        case 0: in = w0; out = o0; break;
        case 1: in = w1; out = o1; break;
        case 2: in = w2; out = o2; break;
        default: in = w3; out = o3; break;
    }
    int i = blockIdx.x * 256 + threadIdx.x;
    float4 v = ((const float4*)in)[i];
    ((__half2*)out)[2*i]   = __floats2half2_rn(v.x, v.y);
    ((__half2*)out)[2*i+1] = __floats2half2_rn(v.z, v.w);
}

// ---------------- adapter projections (wk & wv in one launch, fp32) ---------
__global__ __launch_bounds__(256) void adapter_proj2(const float* __restrict__ adp,
                                                     const float* __restrict__ wk,
                                                     const float* __restrict__ wv)
{
    const int lane = threadIdx.x & 31;
    const int n = blockIdx.x * 8 + (threadIdx.x >> 5);
    const float* w = blockIdx.y ? wv : wk;
    float* out = blockIdx.y ? g_av : g_ak;

    float acc[ALEN];
    #pragma unroll
    for (int j = 0; j < ALEN; j++) acc[j] = 0.f;

    const float4* wr = (const float4*)(w + (long long)n * DIMM);
    for (int k4 = lane; k4 < DIMM/4; k4 += 32) {
        float4 wv4 = wr[k4];
        #pragma unroll
        for (int j = 0; j < ALEN; j++) {
            float4 a4 = ((const float4*)(adp + j * DIMM))[k4];
            acc[j] += a4.x*wv4.x + a4.y*wv4.y + a4.z*wv4.z + a4.w*wv4.w;
        }
    }
    #pragma unroll
    for (int j = 0; j < ALEN; j++) {
        float v = acc[j];
        #pragma unroll
        for (int o = 16; o > 0; o >>= 1) v += __shfl_xor_sync(0xffffffffu, v, o);
        if (lane == 0) out[j * DIMM + n] = v;
    }
}

// ---------------- RoPE on Q: fp32 in -> fp16 out ----------------------------
__global__ void rope_q_kernel(const float* __restrict__ Q, __half* __restrict__ Qh,
                              const float* __restrict__ cs, const float* __restrict__ sn)
{
    int idx = blockIdx.x * blockDim.x + threadIdx.x;   // BS*SEQL*NHEADS*64
    int p = idx & 63;
    int h = (idx >> 6) & 15;
    int r = idx >> 10;
    int q = r & 1023;
    float c = cs[q*64 + p], s = sn[q*64 + p];
    long long base = (long long)r * DIMM + h * HDIM + 2*p;
    float xr = Q[base], xi = Q[base + 1];
    *(__half2*)(Qh + base) = __floats2half2_rn(xr*c - xi*s, xr*s + xi*c);
}

// ---------------- build Kc (rope fused, adapter rows un-roped) -> fp16 ------
__global__ void build_kc_kernel(const float* __restrict__ K,
                                const float* __restrict__ cs, const float* __restrict__ sn)
{
    int idx = blockIdx.x * blockDim.x + threadIdx.x;   // BS*NHEADS*KCAT*64
    int p = idx & 63;
    int rz = idx >> 6;
    int r = rz % KCAT;
    int z = rz / KCAT;
    int b = z >> 4, h = z & 15;
    __half2 out = __floats2half2_rn(0.f, 0.f);
    if (r < ALEN) {
        out = __floats2half2_rn(g_ak[r*DIMM + h*HDIM + 2*p], g_ak[r*DIMM + h*HDIM + 2*p + 1]);
    } else if (r < ALEN + SEQL) {
        int q = r - ALEN;
        float c = cs[q*64 + p], s = sn[q*64 + p];
        long long base = (long long)(b*SEQL + q) * DIMM + h*HDIM + 2*p;
        float xr = K[base], xi = K[base + 1];
        out = __floats2half2_rn(xr*c - xi*s, xr*s + xi*c);
    }
    *(__half2*)(g_Kch + (long long)z*KCAT*HDIM + r*HDIM + 2*p) = out;
}

// ---------------- transposed [adapter|values|pad] V -> fp16 g_Vth[z][d][k] --
__global__ void transpose_v_kernel(const float* __restrict__ V)
{
    __shared__ float tile[32][33];
    int z = blockIdx.z;
    int b = z >> 4, h = z & 15;
    int kt = blockIdx.x * 32, dt = blockIdx.y * 32;
    int tx = threadIdx.x, ty = threadIdx.y;   // 32 x 8
    #pragma unroll
    for (int j = 0; j < 4; j++) {
        int k = kt + ty + 8*j;
        int d = dt + tx;
        float v = 0.f;
        if (k < ALEN) v = g_av[k * DIMM + h * HDIM + d];
        else if (k < ALEN + SEQL)
            v = V[((long long)(b * SEQL + k - ALEN)) * DIMM + h * HDIM + d];
        tile[ty + 8*j][tx] = v;
    }
    __syncthreads();
    #pragma unroll
    for (int j = 0; j < 4; j++) {
        int d = dt + ty + 8*j;
        g_Vth[((long long)z * HDIM + d) * KCAT + kt + tx] = __float2half(tile[tx][ty + 8*j]);
    }
}

// ---------------- softmax: fp32 scores in, fp16 probs out -------------------
__global__ void softmax_kernel(const float* __restrict__ S,
                               const float* __restrict__ gate1,
                               const float* __restrict__ gate2,
                               const int*   __restrict__ vsp)
{
    int z = blockIdx.x >> 10;
    int q = blockIdx.x & 1023;
    int h = z & 15;
    const float* row = S + (long long)blockIdx.x * KCAT;
    __half* hrow = g_Ph + (long long)blockIdx.x * KCAT;
    int tid = threadIdx.x;
    int vs = *vsp;
    const float scale = 0.08838834764831843f;   // 1/sqrt(128)
    float g2 = gate2[h];
    bool grow = (q >= vs + MAXF);

    float vals[4];
    float lmax = -1e30f;
    #pragma unroll
    for (int i = 0; i < 4; i++) {
        int k = tid + i * 256;
        float v = -1e30f;
        if (k <= q) {
            v = row[ALEN + k] * scale;
            if (grow && k >= vs && k < vs + MAXF) v += g2;
        }
        vals[i] = v;  lmax = fmaxf(lmax, v);
    }
    __shared__ float red[256];
    red[tid] = lmax; __syncthreads();
    for (int s = 128; s > 0; s >>= 1) {
        if (tid < s) red[tid] = fmaxf(red[tid], red[tid + s]);
        __syncthreads();
    }
    float rmax = red[0]; __syncthreads();

    float lsum = 0.f;
    #pragma unroll
    for (int i = 0; i < 4; i++) {
        int k = tid + i * 256;
        float e = (k <= q) ? expf(vals[i] - rmax) : 0.f;
        vals[i] = e;  lsum += e;
    }
    red[tid] = lsum; __syncthreads();
    for (int s = 128; s > 0; s >>= 1) {
        if (tid < s) red[tid] += red[tid + s];
        __syncthreads();
    }
    float inv = 1.0f / red[0];

    #pragma unroll
    for (int i = 0; i < 4; i++) {
        int k = tid + i * 256;
        hrow[ALEN + k] = __float2half(vals[i] * inv);
    }
    if (tid < KCAT - ALEN - SEQL) hrow[ALEN + SEQL + tid] = __float2half(0.f);

    if (tid == 0) {
        float g1 = tanhf(gate1[h]);
        float a[ALEN]; float am = -1e30f;
        #pragma unroll
        for (int j = 0; j < ALEN; j++) { a[j] = row[j] * scale; am = fmaxf(am, a[j]); }
        float s = 0.f;
        #pragma unroll
        for (int j = 0; j < ALEN; j++) { a[j] = expf(a[j] - am); s += a[j]; }
        float sc = g1 / s;
        #pragma unroll
        for (int j = 0; j < ALEN; j++) hrow[j] = __float2half(a[j] * sc);
    }
}

// ---------------- launch -----------------------------------------------------
extern "C" void kernel_launch(void* const* d_in, const int* in_sizes, int n_in,
                              void* d_out, int out_size)
{
    const float* x   = (const float*)d_in[0];
    const float* adp = (const float*)d_in[1];
    /* d_in[2] = mask: equivalent to hard causal mask, recomputed on device */
    const float* fc  = (const float*)d_in[3];
    const float* fs  = (const float*)d_in[4];
    const float* wq  = (const float*)d_in[5];
    const float* wk  = (const float*)d_in[6];
    const float* wv  = (const float*)d_in[7];
    const float* wo  = (const float*)d_in[8];
    const float* g1  = (const float*)d_in[9];
    const float* g2  = (const float*)d_in[10];
    const int*   vsp = (const int*)d_in[11];
    float* out = (float*)d_out;

    float *Qp, *Kp, *Vp, *Sp;
    __half *xh, *wqh, *wkh, *wvh, *woh, *Qhp, *Kchp, *Vthp, *Php, *Ohp;
    cudaGetSymbolAddress((void**)&Qp,  g_Q);
    cudaGetSymbolAddress((void**)&Kp,  g_K);
    cudaGetSymbolAddress((void**)&Vp,  g_V);
    cudaGetSymbolAddress((void**)&Sp,  g_S);
    cudaGetSymbolAddress((void**)&xh,  g_xh);
    cudaGetSymbolAddress((void**)&wqh, g_wqh);
    cudaGetSymbolAddress((void**)&wkh, g_wkh);
    cudaGetSymbolAddress((void**)&wvh, g_wvh);
    cudaGetSymbolAddress((void**)&woh, g_woh);
    cudaGetSymbolAddress((void**)&Qhp, g_Qh);
    cudaGetSymbolAddress((void**)&Kchp, g_Kch);
    cudaGetSymbolAddress((void**)&Vthp, g_Vth);
    cudaGetSymbolAddress((void**)&Php, g_Ph);
    cudaGetSymbolAddress((void**)&Ohp, g_Oh);

    cudaFuncSetAttribute((const void*)hgemm<float,false,false>, cudaFuncAttributeMaxDynamicSharedMemorySize, HG_SMEM);
    cudaFuncSetAttribute((const void*)hgemm<float,true,false>,  cudaFuncAttributeMaxDynamicSharedMemorySize, HG_SMEM);
    cudaFuncSetAttribute((const void*)hgemm<__half,false,true>, cudaFuncAttributeMaxDynamicSharedMemorySize, HG_SMEM);

    // fp32 -> fp16 conversions
    f2h_kernel<<<BS*SEQL*DIMM/1024, 256>>>(x, xh);
    f2h4_kernel<<<dim3(DIMM*DIMM/1024, 4), 256>>>(wq, wk, wv, wo, wqh, wkh, wvh, woh);

    // QKV projections: fp32 out
    dim3 gproj(DIMM/128, (BS*SEQL)/128, 1);
    hgemm<float,false,false><<<gproj, 256, HG_SMEM>>>(xh, wqh, Qp, DIMM, DIMM, DIMM, DIMM, 0,0,0,0,0,0, 1);
    hgemm<float,false,false><<<gproj, 256, HG_SMEM>>>(xh, wkh, Kp, DIMM, DIMM, DIMM, DIMM, 0,0,0,0,0,0, 1);
    hgemm<float,false,false><<<gproj, 256, HG_SMEM>>>(xh, wvh, Vp, DIMM, DIMM, DIMM, DIMM, 0,0,0,0,0,0, 1);

    adapter_proj2<<<dim3(DIMM/8, 2), 256>>>(adp, wk, wv);

    rope_q_kernel<<<BS*SEQL*NHEADS*64/256, 256>>>(Qp, Qhp, fc, fs);
    build_kc_kernel<<<(BS*NHEADS*KCAT*64)/256, 256>>>(Kp, fc, fs);
    transpose_v_kernel<<<dim3(KCAT/32, HDIM/32, BS*NHEADS), dim3(32, 8)>>>(Vp);

    // scores: per z: S(1024x1152) = Qh(1024x128) @ Kch^T  (causal tile skip)
    hgemm<float,true,false><<<dim3(KCAT/128, SEQL/128, BS*NHEADS), 256, HG_SMEM>>>(
        Qhp, Kchp, Sp, HDIM,
        DIMM, HDIM, KCAT,
        (long long)SEQL*DIMM, (long long)HDIM,
        (long long)NHEADS*KCAT*HDIM, (long long)KCAT*HDIM,
        (long long)NHEADS*SEQL*KCAT, (long long)SEQL*KCAT, NHEADS);

    softmax_kernel<<<BS*NHEADS*SEQL, 256>>>(Sp, g1, g2, vsp);

    // attn: per z: Oh(1024x128) = Ph(1024x1152) @ Vth(128x1152)^T  (K-truncated)
    hgemm<__half,false,true><<<dim3(1, SEQL/128, BS*NHEADS), 256, HG_SMEM>>>(
        Php, Vthp, Ohp, KCAT,
        KCAT, KCAT, DIMM,
        (long long)NHEADS*SEQL*KCAT, (long long)SEQL*KCAT,
        (long long)NHEADS*HDIM*KCAT, (long long)HDIM*KCAT,
        (long long)SEQL*DIMM, (long long)HDIM, NHEADS);

    // output projection: fp32 out to d_out
    hgemm<float,false,false><<<gproj, 256, HG_SMEM>>>(Ohp, woh, out, DIMM, DIMM, DIMM, DIMM, 0,0,0,0,0,0, 1);
}

// round 7
// speedup vs baseline: 1.2439x; 1.0587x over previous
#include <cuda_runtime.h>
#include <cuda_fp16.h>
#include <math.h>
#include <stdint.h>

#define DIMM   2048
#define NHEADS 16
#define HDIM   128
#define SEQL   1024
#define BS     2
#define ALEN   10
#define MAXF   10
#define KCAT   1152   /* 10 adapter + 1024 keys + 118 zero pad = 9*128 */

// ---------------- scratch (device globals; no allocation allowed) ----------
__device__ float  g_QKV[3*BS*SEQL*DIMM];     // fp32 Q|K|V slices
__device__ float  g_S [BS*NHEADS*SEQL*KCAT];
__device__ float  g_ak[ALEN*DIMM];
__device__ float  g_av[ALEN*DIMM];
__device__ __half g_xh [BS*SEQL*DIMM];
__device__ __half g_wh [3*DIMM*DIMM];        // wq|wk|wv fp16 contiguous
__device__ __half g_woh[DIMM*DIMM];
__device__ __half g_Qh [BS*SEQL*DIMM];
__device__ __half g_Kch[BS*NHEADS*KCAT*HDIM];
__device__ __half g_Vth[BS*NHEADS*HDIM*KCAT];   // V transposed: [z][d][k]
__device__ __half g_Ph [BS*NHEADS*SEQL*KCAT];
__device__ __half g_Oh [BS*SEQL*DIMM];

// ---------------- PTX helpers ----------------------------------------------
__device__ __forceinline__ uint32_t smem_to_u32(const void* p) {
    uint32_t a;
    asm("{ .reg .u64 t; cvta.to.shared.u64 t, %1; cvt.u32.u64 %0, t; }" : "=r"(a) : "l"(p));
    return a;
}
#define CP16(dst, src) \
    asm volatile("cp.async.cg.shared.global [%0], [%1], 16;" :: "r"(dst), "l"(src))
#define CP_COMMIT() asm volatile("cp.async.commit_group;" ::: "memory")
#define CP_WAIT2()  asm volatile("cp.async.wait_group 2;" ::: "memory")

#define LDSM4(r, a) \
    asm volatile("ldmatrix.sync.aligned.m8n8.x4.shared.b16 {%0,%1,%2,%3},[%4];" \
        : "=r"((r)[0]), "=r"((r)[1]), "=r"((r)[2]), "=r"((r)[3]) : "r"(a))

__device__ __forceinline__ void mma16(float* c, const uint32_t* a, uint32_t b0, uint32_t b1) {
    asm volatile(
        "mma.sync.aligned.m16n8k16.row.col.f32.f16.f16.f32 "
        "{%0,%1,%2,%3},{%4,%5,%6,%7},{%8,%9},{%0,%1,%2,%3};"
        : "+f"(c[0]), "+f"(c[1]), "+f"(c[2]), "+f"(c[3])
        : "r"(a[0]), "r"(a[1]), "r"(a[2]), "r"(a[3]), "r"(b0), "r"(b1));
}

// ---------------- fp16 tensor-core batched GEMM: C = A @ B^T ----------------
// CTA tile 128x128, 8 warps (2m x 4n), warp tile 64x32, BK=32, 4-stage cp.async.
// A: (M,K) half row-major, B: (N,K) half row-major. M,N %128==0, K %32==0.
// smem rows 80B pitch (64B data + 16B pad) -> conflict-free ldmatrix.
#define HG_STAGE 20480
#define HG_SMEM  81920

template <typename OutT, bool CAUSAL, bool TRUNC>
__global__ __launch_bounds__(256, 2) void hgemm(
    const __half* __restrict__ A, const __half* __restrict__ B, OutT* __restrict__ C,
    int K, int lda, int ldb, int ldc,
    long long aSb, long long aSh, long long bSb, long long bSh,
    long long cSb, long long cSh, int nh)
{
    const int m0 = blockIdx.y * 128, n0 = blockIdx.x * 128;
    if (CAUSAL && n0 > m0 + 127 + ALEN) return;   // fully-masked score tile

    extern __shared__ char smem[];
    const uint32_t sb = smem_to_u32(smem);
    int zb = blockIdx.z / nh, zh = blockIdx.z % nh;
    A += zb*aSb + zh*aSh;
    B += zb*bSb + zh*bSh;
    C += zb*cSb + zh*cSh;

    const int tid = threadIdx.x, lane = tid & 31, warp = tid >> 5;
    const int wm = warp & 1, wn = warp >> 1;       // warp tile 64(m) x 32(n)

    const int Keff = TRUNC ? min(K, (m0 + 128 + ALEN + 31) & ~31) : K;
    const int nch = Keff >> 5;                     // >= 4 for all our shapes

    // copy mapping: thread -> row tid>>1, two 16B segs at (tid&1)*32 bytes
    const int crow = tid >> 1;
    const int cseg = (tid & 1) * 2;
    const __half* ag = A + (long long)(m0 + crow) * lda + cseg * 8;
    const __half* bg = B + (long long)(n0 + crow) * ldb + cseg * 8;
    const uint32_t sa = sb + crow*80 + cseg*16;
    const uint32_t sbb = sb + 10240 + crow*80 + cseg*16;

    float acc[4][4][4];
    #pragma unroll
    for (int mi = 0; mi < 4; mi++)
        #pragma unroll
        for (int ni = 0; ni < 4; ni++)
            #pragma unroll
            for (int j = 0; j < 4; j++) acc[mi][ni][j] = 0.f;

    // prologue: stages 0..2
    #pragma unroll
    for (int s = 0; s < 3; s++) {
        CP16(sa  + s*HG_STAGE,      ag + s*32);
        CP16(sa  + s*HG_STAGE + 16, ag + s*32 + 8);
        CP16(sbb + s*HG_STAGE,      bg + s*32);
        CP16(sbb + s*HG_STAGE + 16, bg + s*32 + 8);
        CP_COMMIT();
    }

    const int rsel = lane & 15, csel = lane >> 4;

    for (int c = 0; c < nch; c++) {
        CP_WAIT2();
        __syncthreads();

        const uint32_t abase = sb + (c & 3)*HG_STAGE + (wm*64)*80;
        const uint32_t bbase = sb + (c & 3)*HG_STAGE + 10240 + (wn*32)*80;

        uint32_t a[4][4], b[2][2][4];
        // hoist B fragments for both ks-steps + A for ks0
        #pragma unroll
        for (int nj = 0; nj < 2; nj++)
            LDSM4(b[0][nj], bbase + (nj*16 + rsel)*80 + csel*16);
        #pragma unroll
        for (int nj = 0; nj < 2; nj++)
            LDSM4(b[1][nj], bbase + (nj*16 + rsel)*80 + 32 + csel*16);
        #pragma unroll
        for (int mi = 0; mi < 4; mi++)
            LDSM4(a[mi], abase + (mi*16 + rsel)*80 + csel*16);

        // issue next-chunk copies under the fragment loads
        int nxt = c + 3;
        if (nxt < nch) {
            int s = nxt & 3;
            CP16(sa  + s*HG_STAGE,      ag + nxt*32);
            CP16(sa  + s*HG_STAGE + 16, ag + nxt*32 + 8);
            CP16(sbb + s*HG_STAGE,      bg + nxt*32);
            CP16(sbb + s*HG_STAGE + 16, bg + nxt*32 + 8);
        }
        CP_COMMIT();

        // ks = 0
        #pragma unroll
        for (int mi = 0; mi < 4; mi++)
            #pragma unroll
            for (int ni = 0; ni < 4; ni++)
                mma16(acc[mi][ni], a[mi], b[0][ni>>1][ni&1], b[0][ni>>1][(ni&1)+2]);
        // A fragments for ks = 1 (reuse regs)
        #pragma unroll
        for (int mi = 0; mi < 4; mi++)
            LDSM4(a[mi], abase + (mi*16 + rsel)*80 + 32 + csel*16);
        // ks = 1
        #pragma unroll
        for (int mi = 0; mi < 4; mi++)
            #pragma unroll
            for (int ni = 0; ni < 4; ni++)
                mma16(acc[mi][ni], a[mi], b[1][ni>>1][ni&1], b[1][ni>>1][(ni&1)+2]);
    }

    const int er = lane >> 2, ec = (lane & 3) * 2;
    #pragma unroll
    for (int mi = 0; mi < 4; mi++) {
        #pragma unroll
        for (int ni = 0; ni < 4; ni++) {
            int row = m0 + wm*64 + mi*16 + er;
            int col = n0 + wn*32 + ni*8 + ec;
            float* cc = acc[mi][ni];
            if (sizeof(OutT) == 4) {
                *(float2*)((float*)C + (long long)row * ldc + col) = make_float2(cc[0], cc[1]);
                *(float2*)((float*)C + (long long)(row+8) * ldc + col) = make_float2(cc[2], cc[3]);
            } else {
                *(__half2*)((__half*)C + (long long)row * ldc + col) = __floats2half2_rn(cc[0], cc[1]);
                *(__half2*)((__half*)C + (long long)(row+8) * ldc + col) = __floats2half2_rn(cc[2], cc[3]);
            }
        }
    }
}

// ---------------- fp32 -> fp16 conversion -----------------------------------
__global__ void f2h_kernel(const float* __restrict__ in, __half* __restrict__ out) {
    int i = blockIdx.x * 256 + threadIdx.x;
    float4 v = ((const float4*)in)[i];
    ((__half2*)out)[2*i]   = __floats2half2_rn(v.x, v.y);
    ((__half2*)out)[2*i+1] = __floats2half2_rn(v.z, v.w);
}

// all 4 weight matrices in one launch; wq/wk/wv into contiguous g_wh
__global__ void f2h4_kernel(const float* __restrict__ w0, const float* __restrict__ w1,
                            const float* __restrict__ w2, const float* __restrict__ w3,
                            __half* __restrict__ wh, __half* __restrict__ woh) {
    const float* in;  __half* out;
    switch (blockIdx.y) {
        case 0: in = w0; out = wh; break;
        case 1: in = w1; out = wh + (long long)DIMM*DIMM; break;
        case 2: in = w2; out = wh + 2LL*DIMM*DIMM; break;
        default: in = w3; out = woh; break;
    }
    int i = blockIdx.x * 256 + threadIdx.x;
    float4 v = ((const float4*)in)[i];
    ((__half2*)out)[2*i]   = __floats2half2_rn(v.x, v.y);
    ((__half2*)out)[2*i+1] = __floats2half2_rn(v.z, v.w);
}

// ---------------- adapter projections: fp16 weights, fp32 accumulate --------
__global__ __launch_bounds__(256) void adapter_proj2(const float* __restrict__ adp)
{
    const int lane = threadIdx.x & 31;
    const int n = blockIdx.x * 8 + (threadIdx.x >> 5);
    const __half* w = g_wh + (blockIdx.y + 1) * (long long)DIMM*DIMM;   // 1=wk, 2=wv
    float* out = blockIdx.y ? g_av : g_ak;

    float acc[ALEN];
    #pragma unroll
    for (int j = 0; j < ALEN; j++) acc[j] = 0.f;

    const uint4* wr = (const uint4*)(w + (long long)n * DIMM);   // 8 halves each
    for (int k8 = lane; k8 < DIMM/8; k8 += 32) {
        uint4 wv4 = wr[k8];
        __half2 h0 = *(__half2*)&wv4.x, h1 = *(__half2*)&wv4.y;
        __half2 h2 = *(__half2*)&wv4.z, h3 = *(__half2*)&wv4.w;
        float w0 = __half2float(h0.x), w1 = __half2float(h0.y);
        float w2 = __half2float(h1.x), w3 = __half2float(h1.y);
        float w4 = __half2float(h2.x), w5 = __half2float(h2.y);
        float w6 = __half2float(h3.x), w7 = __half2float(h3.y);
        #pragma unroll
        for (int j = 0; j < ALEN; j++) {
            const float4* ap = (const float4*)(adp + j * DIMM + k8 * 8);
            float4 a0 = ap[0], a1 = ap[1];
            acc[j] += a0.x*w0 + a0.y*w1 + a0.z*w2 + a0.w*w3
                    + a1.x*w4 + a1.y*w5 + a1.z*w6 + a1.w*w7;
        }
    }
    #pragma unroll
    for (int j = 0; j < ALEN; j++) {
        float v = acc[j];
        #pragma unroll
        for (int o = 16; o > 0; o >>= 1) v += __shfl_xor_sync(0xffffffffu, v, o);
        if (lane == 0) out[j * DIMM + n] = v;
    }
}

// ---------------- RoPE on Q: fp32 in -> fp16 out ----------------------------
__global__ void rope_q_kernel(const float* __restrict__ Q, __half* __restrict__ Qh,
                              const float* __restrict__ cs, const float* __restrict__ sn)
{
    int idx = blockIdx.x * blockDim.x + threadIdx.x;   // BS*SEQL*NHEADS*64
    int p = idx & 63;
    int h = (idx >> 6) & 15;
    int r = idx >> 10;
    int q = r & 1023;
    float c = cs[q*64 + p], s = sn[q*64 + p];
    long long base = (long long)r * DIMM + h * HDIM + 2*p;
    float xr = Q[base], xi = Q[base + 1];
    *(__half2*)(Qh + base) = __floats2half2_rn(xr*c - xi*s, xr*s + xi*c);
}

// ---------------- build Kc (rope fused, adapter rows un-roped) -> fp16 ------
__global__ void build_kc_kernel(const float* __restrict__ K,
                                const float* __restrict__ cs, const float* __restrict__ sn)
{
    int idx = blockIdx.x * blockDim.x + threadIdx.x;   // BS*NHEADS*KCAT*64
    int p = idx & 63;
    int rz = idx >> 6;
    int r = rz % KCAT;
    int z = rz / KCAT;
    int b = z >> 4, h = z & 15;
    __half2 out = __floats2half2_rn(0.f, 0.f);
    if (r < ALEN) {
        out = __floats2half2_rn(g_ak[r*DIMM + h*HDIM + 2*p], g_ak[r*DIMM + h*HDIM + 2*p + 1]);
    } else if (r < ALEN + SEQL) {
        int q = r - ALEN;
        float c = cs[q*64 + p], s = sn[q*64 + p];
        long long base = (long long)(b*SEQL + q) * DIMM + h*HDIM + 2*p;
        float xr = K[base], xi = K[base + 1];
        out = __floats2half2_rn(xr*c - xi*s, xr*s + xi*c);
    }
    *(__half2*)(g_Kch + (long long)z*KCAT*HDIM + r*HDIM + 2*p) = out;
}

// ---------------- transposed [adapter|values|pad] V -> fp16 g_Vth[z][d][k] --
__global__ void transpose_v_kernel(const float* __restrict__ V)
{
    __shared__ float tile[32][33];
    int z = blockIdx.z;
    int b = z >> 4, h = z & 15;
    int kt = blockIdx.x * 32, dt = blockIdx.y * 32;
    int tx = threadIdx.x, ty = threadIdx.y;   // 32 x 8
    #pragma unroll
    for (int j = 0; j < 4; j++) {
        int k = kt + ty + 8*j;
        int d = dt + tx;
        float v = 0.f;
        if (k < ALEN) v = g_av[k * DIMM + h * HDIM + d];
        else if (k < ALEN + SEQL)
            v = V[((long long)(b * SEQL + k - ALEN)) * DIMM + h * HDIM + d];
        tile[ty + 8*j][tx] = v;
    }
    __syncthreads();
    #pragma unroll
    for (int j = 0; j < 4; j++) {
        int d = dt + ty + 8*j;
        g_Vth[((long long)z * HDIM + d) * KCAT + kt + tx] = __float2half(tile[tx][ty + 8*j]);
    }
}

// ---------------- softmax: warp per row, shfl-only reductions ---------------
__global__ __launch_bounds__(256) void softmax_kernel(
    const float* __restrict__ S,
    const float* __restrict__ gate1,
    const float* __restrict__ gate2,
    const int*   __restrict__ vsp)
{
    const int rowid = blockIdx.x * 8 + (threadIdx.x >> 5);   // BS*NHEADS*SEQL rows
    const int lane = threadIdx.x & 31;
    const int z = rowid >> 10, q = rowid & 1023, h = z & 15;
    const float* row = S + (long long)rowid * KCAT;
    __half* hrow = g_Ph + (long long)rowid * KCAT;
    const int vs = *vsp;
    const float scale = 0.08838834764831843f;   // 1/sqrt(128)
    const float g2 = gate2[h];
    const bool grow = (q >= vs + MAXF);

    float e[32];
    float lmax = -1e30f;
    #pragma unroll
    for (int i = 0; i < 32; i++) {
        int k = i*32 + lane;
        float v = -1e30f;
        if (k <= q) {
            v = row[ALEN + k] * scale;
            if (grow && k >= vs && k < vs + MAXF) v += g2;
        }
        e[i] = v;  lmax = fmaxf(lmax, v);
    }
    #pragma unroll
    for (int o = 16; o > 0; o >>= 1) lmax = fmaxf(lmax, __shfl_xor_sync(0xffffffffu, lmax, o));

    float lsum = 0.f;
    #pragma unroll
    for (int i = 0; i < 32; i++) {
        int k = i*32 + lane;
        float x = (k <= q) ? expf(e[i] - lmax) : 0.f;
        e[i] = x;  lsum += x;
    }
    #pragma unroll
    for (int o = 16; o > 0; o >>= 1) lsum += __shfl_xor_sync(0xffffffffu, lsum, o);
    float inv = 1.0f / lsum;

    #pragma unroll
    for (int i = 0; i < 32; i++)
        hrow[ALEN + i*32 + lane] = __float2half(e[i] * inv);
    for (int k = SEQL + lane; k < KCAT - ALEN; k += 32)     // zero pad cols
        hrow[ALEN + k] = __float2half(0.f);

    // adapter segment: separate softmax * tanh(gate1[h])
    float av = (lane < ALEN) ? row[lane] * scale : -1e30f;
    float am = av;
    #pragma unroll
    for (int o = 16; o > 0; o >>= 1) am = fmaxf(am, __shfl_xor_sync(0xffffffffu, am, o));
    float ae = (lane < ALEN) ? expf(av - am) : 0.f;
    float as = ae;
    #pragma unroll
    for (int o = 16; o > 0; o >>= 1) as += __shfl_xor_sync(0xffffffffu, as, o);
    if (lane < ALEN) hrow[lane] = __float2half(ae * tanhf(gate1[h]) / as);
}

// ---------------- launch -----------------------------------------------------
extern "C" void kernel_launch(void* const* d_in, const int* in_sizes, int n_in,
                              void* d_out, int out_size)
{
    const float* x   = (const float*)d_in[0];
    const float* adp = (const float*)d_in[1];
    /* d_in[2] = mask: equivalent to hard causal mask, recomputed on device */
    const float* fc  = (const float*)d_in[3];
    const float* fs  = (const float*)d_in[4];
    const float* wq  = (const float*)d_in[5];
    const float* wk  = (const float*)d_in[6];
    const float* wv  = (const float*)d_in[7];
    const float* wo  = (const float*)d_in[8];
    const float* g1  = (const float*)d_in[9];
    const float* g2  = (const float*)d_in[10];
    const int*   vsp = (const int*)d_in[11];
    float* out = (float*)d_out;

    float *QKVp, *Sp;
    __half *xh, *wh, *woh, *Qhp, *Kchp, *Vthp, *Php, *Ohp;
    cudaGetSymbolAddress((void**)&QKVp, g_QKV);
    cudaGetSymbolAddress((void**)&Sp,  g_S);
    cudaGetSymbolAddress((void**)&xh,  g_xh);
    cudaGetSymbolAddress((void**)&wh,  g_wh);
    cudaGetSymbolAddress((void**)&woh, g_woh);
    cudaGetSymbolAddress((void**)&Qhp, g_Qh);
    cudaGetSymbolAddress((void**)&Kchp, g_Kch);
    cudaGetSymbolAddress((void**)&Vthp, g_Vth);
    cudaGetSymbolAddress((void**)&Php, g_Ph);
    cudaGetSymbolAddress((void**)&Ohp, g_Oh);

    float* Qp = QKVp;
    float* Kp = QKVp + (long long)BS*SEQL*DIMM;
    float* Vp = QKVp + 2LL*BS*SEQL*DIMM;

    cudaFuncSetAttribute((const void*)hgemm<float,false,false>, cudaFuncAttributeMaxDynamicSharedMemorySize, HG_SMEM);
    cudaFuncSetAttribute((const void*)hgemm<float,true,false>,  cudaFuncAttributeMaxDynamicSharedMemorySize, HG_SMEM);
    cudaFuncSetAttribute((const void*)hgemm<__half,false,true>, cudaFuncAttributeMaxDynamicSharedMemorySize, HG_SMEM);

    // fp32 -> fp16 conversions
    f2h_kernel<<<BS*SEQL*DIMM/1024, 256>>>(x, xh);
    f2h4_kernel<<<dim3(DIMM*DIMM/1024, 4), 256>>>(wq, wk, wv, wo, wh, woh);

    // QKV projections fused: z in {0,1,2} selects weight & output slice
    hgemm<float,false,false><<<dim3(DIMM/128, (BS*SEQL)/128, 3), 256, HG_SMEM>>>(
        xh, wh, QKVp, DIMM, DIMM, DIMM, DIMM,
        0, 0, 0, (long long)DIMM*DIMM,
        0, (long long)BS*SEQL*DIMM, 3);

    adapter_proj2<<<dim3(DIMM/8, 2), 256>>>(adp);

    rope_q_kernel<<<BS*SEQL*NHEADS*64/256, 256>>>(Qp, Qhp, fc, fs);
    build_kc_kernel<<<(BS*NHEADS*KCAT*64)/256, 256>>>(Kp, fc, fs);
    transpose_v_kernel<<<dim3(KCAT/32, HDIM/32, BS*NHEADS), dim3(32, 8)>>>(Vp);

    // scores: per z: S(1024x1152) = Qh(1024x128) @ Kch^T  (causal tile skip)
    hgemm<float,true,false><<<dim3(KCAT/128, SEQL/128, BS*NHEADS), 256, HG_SMEM>>>(
        Qhp, Kchp, Sp, HDIM,
        DIMM, HDIM, KCAT,
        (long long)SEQL*DIMM, (long long)HDIM,
        (long long)NHEADS*KCAT*HDIM, (long long)KCAT*HDIM,
        (long long)NHEADS*SEQL*KCAT, (long long)SEQL*KCAT, NHEADS);

    softmax_kernel<<<BS*NHEADS*SEQL/8, 256>>>(Sp, g1, g2, vsp);

    // attn: per z: Oh(1024x128) = Ph(1024x1152) @ Vth(128x1152)^T  (K-truncated)
    hgemm<__half,false,true><<<dim3(1, SEQL/128, BS*NHEADS), 256, HG_SMEM>>>(
        Php, Vthp, Ohp, KCAT,
        KCAT, KCAT, DIMM,
        (long long)NHEADS*SEQL*KCAT, (long long)SEQL*KCAT,
        (long long)NHEADS*HDIM*KCAT, (long long)HDIM*KCAT,
        (long long)SEQL*DIMM, (long long)HDIM, NHEADS);

    // output projection: fp32 out to d_out
    hgemm<float,false,false><<<dim3(DIMM/128, (BS*SEQL)/128, 1), 256, HG_SMEM>>>(
        Ohp, woh, out, DIMM, DIMM, DIMM, DIMM, 0,0,0,0,0,0, 1);
}

// round 10
// speedup vs baseline: 1.3197x; 1.0609x over previous
#include <cuda_runtime.h>
#include <cuda_fp16.h>
#include <math.h>
#include <stdint.h>

#define DIMM   2048
#define NHEADS 16
#define HDIM   128
#define SEQL   1024
#define BS     2
#define ALEN   10
#define MAXF   10
#define KCAT   1152   /* 10 adapter + 1024 keys + 118 zero pad = 9*128 */
#define MPAD   (BS*SEQL + 128)   /* 2176: x rows + adapter row tile */

// ---------------- scratch (device globals; no allocation allowed) ----------
__device__ float  g_QKV[3*MPAD*DIMM];        // fp32 Q|K|V slices (2176 rows each)
__device__ float  g_S [BS*NHEADS*SEQL*KCAT];
__device__ __half g_xh [MPAD*DIMM];          // x (2048) | adapter (10) | zeros
__device__ __half g_wh [3*DIMM*DIMM];        // wq|wk|wv fp16 contiguous
__device__ __half g_woh[DIMM*DIMM];
__device__ __half g_Qh [BS*SEQL*DIMM];
__device__ __half g_Kch[BS*NHEADS*KCAT*HDIM];
__device__ __half g_Vth[BS*NHEADS*HDIM*KCAT];   // V transposed: [z][d][k]
__device__ __half g_Ph [BS*NHEADS*SEQL*KCAT];
__device__ __half g_Oh [BS*SEQL*DIMM];

// ---------------- PTX helpers ----------------------------------------------
__device__ __forceinline__ uint32_t smem_to_u32(const void* p) {
    uint32_t a;
    asm("{ .reg .u64 t; cvta.to.shared.u64 t, %1; cvt.u32.u64 %0, t; }" : "=r"(a) : "l"(p));
    return a;
}
#define CP16(dst, src) \
    asm volatile("cp.async.cg.shared.global [%0], [%1], 16;" :: "r"(dst), "l"(src))
#define CP_COMMIT() asm volatile("cp.async.commit_group;" ::: "memory")
#define CP_WAIT2()  asm volatile("cp.async.wait_group 2;" ::: "memory")

#define LDSM4(r, a) \
    asm volatile("ldmatrix.sync.aligned.m8n8.x4.shared.b16 {%0,%1,%2,%3},[%4];" \
        : "=r"((r)[0]), "=r"((r)[1]), "=r"((r)[2]), "=r"((r)[3]) : "r"(a))

__device__ __forceinline__ void mma16(float* c, const uint32_t* a, uint32_t b0, uint32_t b1) {
    asm volatile(
        "mma.sync.aligned.m16n8k16.row.col.f32.f16.f16.f32 "
        "{%0,%1,%2,%3},{%4,%5,%6,%7},{%8,%9},{%0,%1,%2,%3};"
        : "+f"(c[0]), "+f"(c[1]), "+f"(c[2]), "+f"(c[3])
        : "r"(a[0]), "r"(a[1]), "r"(a[2]), "r"(a[3]), "r"(b0), "r"(b1));
}

// ---------------- fp16 tensor-core batched GEMM: C = A @ B^T ----------------
// CTA tile 128x128, 8 warps (2m x 4n), warp tile 64x32, BK=32, 4-stage cp.async.
// A: (M,K) half row-major, B: (N,K) half row-major. M,N %128==0, K %32==0.
// smem rows 80B pitch (64B data + 16B pad) -> conflict-free ldmatrix.
#define HG_STAGE 20480
#define HG_SMEM  81920

template <typename OutT, bool CAUSAL, bool TRUNC>
__global__ __launch_bounds__(256, 2) void hgemm(
    const __half* __restrict__ A, const __half* __restrict__ B, OutT* __restrict__ C,
    int K, int lda, int ldb, int ldc,
    long long aSb, long long aSh, long long bSb, long long bSh,
    long long cSb, long long cSh, int nh)
{
    const int m0 = blockIdx.y * 128, n0 = blockIdx.x * 128;
    if (CAUSAL && n0 > m0 + 127 + ALEN) return;   // fully-masked score tile

    extern __shared__ char smem[];
    const uint32_t sb = smem_to_u32(smem);
    int zb = blockIdx.z / nh, zh = blockIdx.z % nh;
    A += zb*aSb + zh*aSh;
    B += zb*bSb + zh*bSh;
    C += zb*cSb + zh*cSh;

    const int tid = threadIdx.x, lane = tid & 31, warp = tid >> 5;
    const int wm = warp & 1, wn = warp >> 1;       // warp tile 64(m) x 32(n)

    const int Keff = TRUNC ? min(K, (m0 + 128 + ALEN + 31) & ~31) : K;
    const int nch = Keff >> 5;                     // >= 4 for all our shapes

    // copy mapping: thread -> row tid>>1, two 16B segs at (tid&1)*32 bytes
    const int crow = tid >> 1;
    const int cseg = (tid & 1) * 2;
    const __half* ag = A + (long long)(m0 + crow) * lda + cseg * 8;
    const __half* bg = B + (long long)(n0 + crow) * ldb + cseg * 8;
    const uint32_t sa = sb + crow*80 + cseg*16;
    const uint32_t sbb = sb + 10240 + crow*80 + cseg*16;

    float acc[4][4][4];
    #pragma unroll
    for (int mi = 0; mi < 4; mi++)
        #pragma unroll
        for (int ni = 0; ni < 4; ni++)
            #pragma unroll
            for (int j = 0; j < 4; j++) acc[mi][ni][j] = 0.f;

    // prologue: stages 0..2
    #pragma unroll
    for (int s = 0; s < 3; s++) {
        CP16(sa  + s*HG_STAGE,      ag + s*32);
        CP16(sa  + s*HG_STAGE + 16, ag + s*32 + 8);
        CP16(sbb + s*HG_STAGE,      bg + s*32);
        CP16(sbb + s*HG_STAGE + 16, bg + s*32 + 8);
        CP_COMMIT();
    }

    const int rsel = lane & 15, csel = lane >> 4;

    for (int c = 0; c < nch; c++) {
        CP_WAIT2();
        __syncthreads();

        const uint32_t abase = sb + (c & 3)*HG_STAGE + (wm*64)*80;
        const uint32_t bbase = sb + (c & 3)*HG_STAGE + 10240 + (wn*32)*80;

        uint32_t a[4][4], b[2][2][4];
        // hoist B fragments for both ks-steps + A for ks0
        #pragma unroll
        for (int nj = 0; nj < 2; nj++)
            LDSM4(b[0][nj], bbase + (nj*16 + rsel)*80 + csel*16);
        #pragma unroll
        for (int nj = 0; nj < 2; nj++)
            LDSM4(b[1][nj], bbase + (nj*16 + rsel)*80 + 32 + csel*16);
        #pragma unroll
        for (int mi = 0; mi < 4; mi++)
            LDSM4(a[mi], abase + (mi*16 + rsel)*80 + csel*16);

        // issue next-chunk copies under the fragment loads
        int nxt = c + 3;
        if (nxt < nch) {
            int s = nxt & 3;
            CP16(sa  + s*HG_STAGE,      ag + nxt*32);
            CP16(sa  + s*HG_STAGE + 16, ag + nxt*32 + 8);
            CP16(sbb + s*HG_STAGE,      bg + nxt*32);
            CP16(sbb + s*HG_STAGE + 16, bg + nxt*32 + 8);
        }
        CP_COMMIT();

        // ks = 0
        #pragma unroll
        for (int mi = 0; mi < 4; mi++)
            #pragma unroll
            for (int ni = 0; ni < 4; ni++)
                mma16(acc[mi][ni], a[mi], b[0][ni>>1][ni&1], b[0][ni>>1][(ni&1)+2]);
        // A fragments for ks = 1 (reuse regs)
        #pragma unroll
        for (int mi = 0; mi < 4; mi++)
            LDSM4(a[mi], abase + (mi*16 + rsel)*80 + 32 + csel*16);
        // ks = 1
        #pragma unroll
        for (int mi = 0; mi < 4; mi++)
            #pragma unroll
            for (int ni = 0; ni < 4; ni++)
                mma16(acc[mi][ni], a[mi], b[1][ni>>1][ni&1], b[1][ni>>1][(ni&1)+2]);
    }

    const int er = lane >> 2, ec = (lane & 3) * 2;
    #pragma unroll
    for (int mi = 0; mi < 4; mi++) {
        #pragma unroll
        for (int ni = 0; ni < 4; ni++) {
            int row = m0 + wm*64 + mi*16 + er;
            int col = n0 + wn*32 + ni*8 + ec;
            float* cc = acc[mi][ni];
            if (sizeof(OutT) == 4) {
                *(float2*)((float*)C + (long long)row * ldc + col) = make_float2(cc[0], cc[1]);
                *(float2*)((float*)C + (long long)(row+8) * ldc + col) = make_float2(cc[2], cc[3]);
            } else {
                *(__half2*)((__half*)C + (long long)row * ldc + col) = __floats2half2_rn(cc[0], cc[1]);
                *(__half2*)((__half*)C + (long long)(row+8) * ldc + col) = __floats2half2_rn(cc[2], cc[3]);
            }
        }
    }
}

// ---------------- fp32 -> fp16 conversion, 4 float4 per thread (MLP=4) ------
__global__ void f2h_kernel(const float* __restrict__ in, __half* __restrict__ out) {
    int base = blockIdx.x * 1024 + threadIdx.x;
    float4 v[4];
    #pragma unroll
    for (int j = 0; j < 4; j++) v[j] = ((const float4*)in)[base + j*256];
    #pragma unroll
    for (int j = 0; j < 4; j++) {
        int i = base + j*256;
        ((__half2*)out)[2*i]   = __floats2half2_rn(v[j].x, v[j].y);
        ((__half2*)out)[2*i+1] = __floats2half2_rn(v[j].z, v[j].w);
    }
}

// all 4 weight matrices in one launch; wq/wk/wv into contiguous g_wh
__global__ void f2h4_kernel(const float* __restrict__ w0, const float* __restrict__ w1,
                            const float* __restrict__ w2, const float* __restrict__ w3,
                            __half* __restrict__ wh, __half* __restrict__ woh) {
    const float* in;  __half* out;
    switch (blockIdx.y) {
        case 0: in = w0; out = wh; break;
        case 1: in = w1; out = wh + (long long)DIMM*DIMM; break;
        case 2: in = w2; out = wh + 2LL*DIMM*DIMM; break;
        default: in = w3; out = woh; break;
    }
    int base = blockIdx.x * 1024 + threadIdx.x;
    float4 v[4];
    #pragma unroll
    for (int j = 0; j < 4; j++) v[j] = ((const float4*)in)[base + j*256];
    #pragma unroll
    for (int j = 0; j < 4; j++) {
        int i = base + j*256;
        ((__half2*)out)[2*i]   = __floats2half2_rn(v[j].x, v[j].y);
        ((__half2*)out)[2*i+1] = __floats2half2_rn(v[j].z, v[j].w);
    }
}

// ---------------- adapter rows -> xh rows 2048..2175 (10 real + zero pad) ---
__global__ void adapter_fill_kernel(const float* __restrict__ adp) {
    int i = blockIdx.x * 256 + threadIdx.x;     // over 128*2048/8 = 32768 uint4
    int row = i >> 8;                           // 256 8-half chunks per row
    int c8 = (i & 255) * 8;
    __half h[8];
    if (row < ALEN) {
        #pragma unroll
        for (int j = 0; j < 8; j++) h[j] = __float2half(adp[row*DIMM + c8 + j]);
    } else {
        #pragma unroll
        for (int j = 0; j < 8; j++) h[j] = __float2half(0.f);
    }
    *(uint4*)(g_xh + (long long)(BS*SEQL + row)*DIMM + c8) = *(uint4*)h;
}

// ---------------- RoPE on Q: fp32 in -> fp16 out (2 pairs/thread) -----------
__global__ void rope_q_kernel(const float* __restrict__ Q, __half* __restrict__ Qh,
                              const float* __restrict__ cs, const float* __restrict__ sn)
{
    int idx = blockIdx.x * blockDim.x + threadIdx.x;   // BS*SEQL*NHEADS*32
    int pp = (idx & 31) * 2;          // pair base: 0,2,..,62
    int h = (idx >> 5) & 15;
    int r = idx >> 9;                 // global row b*1024+q
    int q = r & 1023;
    float2 c2 = *(const float2*)(cs + q*64 + pp);
    float2 s2 = *(const float2*)(sn + q*64 + pp);
    long long base = (long long)r * DIMM + h * HDIM + 2*pp;
    float4 v = *(const float4*)(Q + base);
    __half2 o0 = __floats2half2_rn(v.x*c2.x - v.y*s2.x, v.x*s2.x + v.y*c2.x);
    __half2 o1 = __floats2half2_rn(v.z*c2.y - v.w*s2.y, v.z*s2.y + v.w*c2.y);
    *(__half2*)(Qh + base)     = o0;
    *(__half2*)(Qh + base + 2) = o1;
}

// ---------------- build Kc (rope fused; adapter rows from K slice) ----------
__global__ void build_kc_kernel(const float* __restrict__ K,
                                const float* __restrict__ cs, const float* __restrict__ sn)
{
    int idx = blockIdx.x * blockDim.x + threadIdx.x;   // BS*NHEADS*KCAT*32
    int pp = (idx & 31) * 2;          // pair base
    int rz = idx >> 5;
    int r = rz % KCAT;
    int z = rz / KCAT;
    int b = z >> 4, h = z & 15;
    __half2 o0 = __floats2half2_rn(0.f, 0.f), o1 = o0;
    if (r < ALEN) {
        float4 v = *(const float4*)(K + (long long)(BS*SEQL + r)*DIMM + h*HDIM + 2*pp);
        o0 = __floats2half2_rn(v.x, v.y);
        o1 = __floats2half2_rn(v.z, v.w);
    } else if (r < ALEN + SEQL) {
        int q = r - ALEN;
        float2 c2 = *(const float2*)(cs + q*64 + pp);
        float2 s2 = *(const float2*)(sn + q*64 + pp);
        float4 v = *(const float4*)(K + (long long)(b*SEQL + q)*DIMM + h*HDIM + 2*pp);
        o0 = __floats2half2_rn(v.x*c2.x - v.y*s2.x, v.x*s2.x + v.y*c2.x);
        o1 = __floats2half2_rn(v.z*c2.y - v.w*s2.y, v.z*s2.y + v.w*c2.y);
    }
    __half* dst = g_Kch + (long long)z*KCAT*HDIM + r*HDIM + 2*pp;
    *(__half2*)dst = o0;
    *(__half2*)(dst + 2) = o1;
}

// ---------------- transposed [adapter|values|pad] V -> fp16 g_Vth[z][d][k] --
__global__ void transpose_v_kernel(const float* __restrict__ V)
{
    __shared__ float tile[32][33];
    int z = blockIdx.z;
    int b = z >> 4, h = z & 15;
    int kt = blockIdx.x * 32, dt = blockIdx.y * 32;
    int tx = threadIdx.x, ty = threadIdx.y;   // 32 x 8
    #pragma unroll
    for (int j = 0; j < 4; j++) {
        int k = kt + ty + 8*j;
        int d = dt + tx;
        float v = 0.f;
        if (k < ALEN) v = V[(long long)(BS*SEQL + k)*DIMM + h*HDIM + d];
        else if (k < ALEN + SEQL)
            v = V[((long long)(b * SEQL + k - ALEN)) * DIMM + h * HDIM + d];
        tile[ty + 8*j][tx] = v;
    }
    __syncthreads();
    #pragma unroll
    for (int j = 0; j < 4; j++) {
        int d = dt + ty + 8*j;
        g_Vth[((long long)z * HDIM + d) * KCAT + kt + tx] = __float2half(tile[tx][ty + 8*j]);
    }
}

// ---------------- softmax: warp per row, shfl-only reductions ---------------
__global__ __launch_bounds__(256) void softmax_kernel(
    const float* __restrict__ S,
    const float* __restrict__ gate1,
    const float* __restrict__ gate2,
    const int*   __restrict__ vsp)
{
    const int rowid = blockIdx.x * 8 + (threadIdx.x >> 5);   // BS*NHEADS*SEQL rows
    const int lane = threadIdx.x & 31;
    const int z = rowid >> 10, q = rowid & 1023, h = z & 15;
    const float* row = S + (long long)rowid * KCAT;
    __half* hrow = g_Ph + (long long)rowid * KCAT;
    const int vs = *vsp;
    const float scale = 0.08838834764831843f;   // 1/sqrt(128)
    const float g2 = gate2[h];
    const bool grow = (q >= vs + MAXF);

    float e[32];
    float lmax = -1e30f;
    #pragma unroll
    for (int i = 0; i < 32; i++) {
        int k = i*32 + lane;
        float v = -1e30f;
        if (k <= q) {
            v = row[ALEN + k] * scale;
            if (grow && k >= vs && k < vs + MAXF) v += g2;
        }
        e[i] = v;  lmax = fmaxf(lmax, v);
    }
    #pragma unroll
    for (int o = 16; o > 0; o >>= 1) lmax = fmaxf(lmax, __shfl_xor_sync(0xffffffffu, lmax, o));

    float lsum = 0.f;
    #pragma unroll
    for (int i = 0; i < 32; i++) {
        int k = i*32 + lane;
        float x = (k <= q) ? expf(e[i] - lmax) : 0.f;
        e[i] = x;  lsum += x;
    }
    #pragma unroll
    for (int o = 16; o > 0; o >>= 1) lsum += __shfl_xor_sync(0xffffffffu, lsum, o);
    float inv = 1.0f / lsum;

    #pragma unroll
    for (int i = 0; i < 32; i++)
        hrow[ALEN + i*32 + lane] = __float2half(e[i] * inv);
    for (int k = SEQL + lane; k < KCAT - ALEN; k += 32)     // zero pad cols
        hrow[ALEN + k] = __float2half(0.f);

    // adapter segment: separate softmax * tanh(gate1[h])
    float av = (lane < ALEN) ? row[lane] * scale : -1e30f;
    float am = av;
    #pragma unroll
    for (int o = 16; o > 0; o >>= 1) am = fmaxf(am, __shfl_xor_sync(0xffffffffu, am, o));
    float ae = (lane < ALEN) ? expf(av - am) : 0.f;
    float as = ae;
    #pragma unroll
    for (int o = 16; o > 0; o >>= 1) as += __shfl_xor_sync(0xffffffffu, as, o);
    if (lane < ALEN) hrow[lane] = __float2half(ae * tanhf(gate1[h]) / as);
}

// ---------------- launch -----------------------------------------------------
extern "C" void kernel_launch(void* const* d_in, const int* in_sizes, int n_in,
                              void* d_out, int out_size)
{
    const float* x   = (const float*)d_in[0];
    const float* adp = (const float*)d_in[1];
    /* d_in[2] = mask: equivalent to hard causal mask, recomputed on device */
    const float* fc  = (const float*)d_in[3];
    const float* fs  = (const float*)d_in[4];
    const float* wq  = (const float*)d_in[5];
    const float* wk  = (const float*)d_in[6];
    const float* wv  = (const float*)d_in[7];
    const float* wo  = (const float*)d_in[8];
    const float* g1  = (const float*)d_in[9];
    const float* g2  = (const float*)d_in[10];
    const int*   vsp = (const int*)d_in[11];
    float* out = (float*)d_out;

    float *QKVp, *Sp;
    __half *xh, *wh, *woh, *Qhp, *Kchp, *Vthp, *Php, *Ohp;
    cudaGetSymbolAddress((void**)&QKVp, g_QKV);
    cudaGetSymbolAddress((void**)&Sp,  g_S);
    cudaGetSymbolAddress((void**)&xh,  g_xh);
    cudaGetSymbolAddress((void**)&wh,  g_wh);
    cudaGetSymbolAddress((void**)&woh, g_woh);
    cudaGetSymbolAddress((void**)&Qhp, g_Qh);
    cudaGetSymbolAddress((void**)&Kchp, g_Kch);
    cudaGetSymbolAddress((void**)&Vthp, g_Vth);
    cudaGetSymbolAddress((void**)&Php, g_Ph);
    cudaGetSymbolAddress((void**)&Ohp, g_Oh);

    float* Qp = QKVp;
    float* Kp = QKVp + (long long)MPAD*DIMM;
    float* Vp = QKVp + 2LL*MPAD*DIMM;

    cudaFuncSetAttribute((const void*)hgemm<float,false,false>, cudaFuncAttributeMaxDynamicSharedMemorySize, HG_SMEM);
    cudaFuncSetAttribute((const void*)hgemm<float,true,false>,  cudaFuncAttributeMaxDynamicSharedMemorySize, HG_SMEM);
    cudaFuncSetAttribute((const void*)hgemm<__half,false,true>, cudaFuncAttributeMaxDynamicSharedMemorySize, HG_SMEM);

    // fp32 -> fp16 conversions + adapter rows into xh
    f2h_kernel<<<BS*SEQL*DIMM/4096, 256>>>(x, xh);
    f2h4_kernel<<<dim3(DIMM*DIMM/4096, 4), 256>>>(wq, wk, wv, wo, wh, woh);
    adapter_fill_kernel<<<128, 256>>>(adp);

    // QKV projections fused (M=2176 incl. adapter rows); z selects weight/output
    hgemm<float,false,false><<<dim3(DIMM/128, MPAD/128, 3), 256, HG_SMEM>>>(
        xh, wh, QKVp, DIMM, DIMM, DIMM, DIMM,
        0, 0, 0, (long long)DIMM*DIMM,
        0, (long long)MPAD*DIMM, 3);

    rope_q_kernel<<<BS*SEQL*NHEADS*32/256, 256>>>(Qp, Qhp, fc, fs);
    build_kc_kernel<<<(BS*NHEADS*KCAT*32)/256, 256>>>(Kp, fc, fs);
    transpose_v_kernel<<<dim3(KCAT/32, HDIM/32, BS*NHEADS), dim3(32, 8)>>>(Vp);

    // scores: per z: S(1024x1152) = Qh(1024x128) @ Kch^T  (causal tile skip)
    hgemm<float,true,false><<<dim3(KCAT/128, SEQL/128, BS*NHEADS), 256, HG_SMEM>>>(
        Qhp, Kchp, Sp, HDIM,
        DIMM, HDIM, KCAT,
        (long long)SEQL*DIMM, (long long)HDIM,
        (long long)NHEADS*KCAT*HDIM, (long long)KCAT*HDIM,
        (long long)NHEADS*SEQL*KCAT, (long long)SEQL*KCAT, NHEADS);

    softmax_kernel<<<BS*NHEADS*SEQL/8, 256>>>(Sp, g1, g2, vsp);

    // attn: per z: Oh(1024x128) = Ph(1024x1152) @ Vth(128x1152)^T  (K-truncated)
    hgemm<__half,false,true><<<dim3(1, SEQL/128, BS*NHEADS), 256, HG_SMEM>>>(
        Php, Vthp, Ohp, KCAT,
        KCAT, KCAT, DIMM,
        (long long)NHEADS*SEQL*KCAT, (long long)SEQL*KCAT,
        (long long)NHEADS*HDIM*KCAT, (long long)HDIM*KCAT,
        (long long)SEQL*DIMM, (long long)HDIM, NHEADS);

    // output projection: fp32 out to d_out
    hgemm<float,false,false><<<dim3(DIMM/128, (BS*SEQL)/128, 1), 256, HG_SMEM>>>(
        Ohp, woh, out, DIMM, DIMM, DIMM, DIMM, 0,0,0,0,0,0, 1);
}